// round 6
// baseline (speedup 1.0000x reference)
#include <cuda_runtime.h>
#include <cuda_fp16.h>
#include <math.h>

// Problem constants
#define B  32
#define O  64
#define I  2048
#define VO 32
#define VI 16

typedef unsigned long long u64;

// Scratch (device globals: no allocation allowed)
__device__ __half g_uhat[(size_t)B * I * O * VO];  // [b][i][o][v], fp16, 256 MB
__device__ float g_S0[B * O * VO];
__device__ float g_S1[B * O * VO];
__device__ float g_S2[B * O * VO];
__device__ float g_Vacc[B * O * VO];               // v0, then v0+v1

// ---------------------------------------------------------------------------
// helpers
// ---------------------------------------------------------------------------
__device__ __forceinline__ u64 ffma2(u64 a, u64 b, u64 c) {
    u64 d;
    asm("fma.rn.f32x2 %0,%1,%2,%3;" : "=l"(d) : "l"(a), "l"(b), "l"(c));
    return d;
}
__device__ __forceinline__ void upk2(u64 v, float& lo, float& hi) {
    asm("mov.b64 {%0,%1},%2;" : "=f"(lo), "=f"(hi) : "l"(v));
}
__device__ __forceinline__ unsigned int smem_u32(const void* p) {
    return (unsigned int)__cvta_generic_to_shared(p);
}
__device__ __forceinline__ void cp_async16(unsigned int s, const void* g) {
    asm volatile("cp.async.cg.shared.global [%0], [%1], 16;" :: "r"(s), "l"(g));
}
__device__ __forceinline__ void cp_async_wait_all() {
    asm volatile("cp.async.commit_group;");
    asm volatile("cp.async.wait_group 0;");
}

// ---------------------------------------------------------------------------
// Zero the atomic accumulators (graph replays reuse scratch)
// ---------------------------------------------------------------------------
__global__ void zero_kernel() {
    int idx = blockIdx.x * blockDim.x + threadIdx.x;
    if (idx < B * O * VO) {
        g_S0[idx] = 0.0f;
        g_S1[idx] = 0.0f;
        g_S2[idx] = 0.0f;
    }
}

// ---------------------------------------------------------------------------
// P0: u_hat[b,i,o,v] = sum_u W[o,i,v,u] * x[b,i,u], stored fp16.
// Grid (I, O/16), 256 threads. Thread = (b = t>>3, vq = t&7): x[b,i,:] held
// in 8 f32x2 REGISTERS (loaded once), loop over 16 o's reading this thread's
// 64 W floats per o from SMEM. Lanes with equal vq across the 4 b's in a warp
// read identical W bytes -> LDS broadcast (crossbar traffic = W bytes x1).
// vq blocks padded to 272B -> the 8 vq lanes hit 8 distinct 16B chunks per
// 128B bank window -> conflict-free.
// SMEM layout: Ws byte addr = o*2176 + vq*272 + chunk*16  (chunk = 0..15,
// covering v-row r=chunk>>2, u-quad (chunk&3)).
// ---------------------------------------------------------------------------
__global__ void __launch_bounds__(256) p0_kernel(const float* __restrict__ W,
                                                 const float* __restrict__ x) {
    __shared__ float Ws[16 * 544];   // 16 o * 2176 B = 34816 B
    __shared__ float Xs[B * VI];     // 2 KB

    const int i   = blockIdx.x;
    const int o0  = blockIdx.y * 16;
    const int tid = threadIdx.x;

    const unsigned int sW = smem_u32(Ws);
    const unsigned int sX = smem_u32(Xs);

    // W tile: 16 o-rows of 512 floats; 2048 16B-chunks over 256 threads.
#pragma unroll
    for (int k = 0; k < 8; k++) {
        int idx = tid + k * 256;
        int o = idx >> 7;          // 0..15
        int c = idx & 127;         // 16B chunk within the o-row
        unsigned int dst = sW + (unsigned int)(o * 2176 + (c >> 4) * 272 + (c & 15) * 16);
        cp_async16(dst, (const char*)W + ((size_t)(o0 + o) * I + i) * 2048 + (size_t)c * 16);
    }
    // x tile: Xs[b][u], 128 chunks
    if (tid < 128) {
        cp_async16(sX + (unsigned int)(tid * 16),
                   x + ((size_t)(tid >> 2) * I + i) * VI + (tid & 3) * 4);
    }
    cp_async_wait_all();
    __syncthreads();

    const int b  = tid >> 3;
    const int vq = tid & 7;

    // x[b,i,0..15] -> 8 f32x2 registers (u pairs)
    u64 xp[8];
    {
        const float* xrow = Xs + b * VI;
#pragma unroll
        for (int q = 0; q < 4; q++) {
            ulonglong2 t2 = *(const ulonglong2*)(xrow + q * 4);
            xp[2 * q + 0] = t2.x;
            xp[2 * q + 1] = t2.y;
        }
    }

    const char* wvq = (const char*)Ws + vq * 272;
    const size_t orow = ((size_t)b * I + i) * O + o0;   // u_hat row base (in o units)

#pragma unroll 2
    for (int o = 0; o < 16; o++) {
        const char* wo = wvq + o * 2176;
        u64 acc[4] = {0ull, 0ull, 0ull, 0ull};
#pragma unroll
        for (int q = 0; q < 16; q++) {
            ulonglong2 t2 = *(const ulonglong2*)(wo + q * 16);
            const int r = q >> 2;
            const int p = (q & 3) * 2;
            acc[r] = ffma2(t2.x, xp[p + 0], acc[r]);
            acc[r] = ffma2(t2.y, xp[p + 1], acc[r]);
        }
        float l0, h0, l1, h1, l2, h2, l3, h3;
        upk2(acc[0], l0, h0); upk2(acc[1], l1, h1);
        upk2(acc[2], l2, h2); upk2(acc[3], l3, h3);
        __half2 pa = __floats2half2_rn(l0 + h0, l1 + h1);
        __half2 pb = __floats2half2_rn(l2 + h2, l3 + h3);
        float2 pk;
        pk.x = __uint_as_float(*(unsigned int*)&pa);
        pk.y = __uint_as_float(*(unsigned int*)&pb);
        size_t hidx = (orow + o) * VO + (size_t)vq * 4;
        __stcs((float2*)(g_uhat + hidx), pk);
    }
}

// ---------------------------------------------------------------------------
// S0 pass: S0[b,o,v] = sum_i u_hat. Thread owns (b,o,q,c): q = uint2 column
// (4 v's), c one of 4 i-chunks; atomicAdd tail into zeroed S0. 65536 threads.
// ---------------------------------------------------------------------------
__global__ void __launch_bounds__(256) s0_kernel() {
    int t = blockIdx.x * 256 + threadIdx.x;   // 0 .. 65535
    int q = t & 7;
    int o = (t >> 3) & 63;
    int c = (t >> 9) & 3;
    int b = t >> 11;

    const uint2* up = (const uint2*)g_uhat;
    size_t base = (((size_t)b * I + (size_t)c * 512) * O + (size_t)o) * 8 + q;
    const size_t istride = (size_t)O * 8;

    float a0 = 0.f, a1 = 0.f, a2 = 0.f, a3 = 0.f;
#pragma unroll 8
    for (int i = 0; i < 512; i++) {
        uint2 h = __ldcs(&up[base + (size_t)i * istride]);
        float2 f0 = __half22float2(*(const __half2*)&h.x);
        float2 f1 = __half22float2(*(const __half2*)&h.y);
        a0 += f0.x; a1 += f0.y; a2 += f1.x; a3 += f1.y;
    }
    float* sp = g_S0 + (size_t)(b * O + o) * VO + q * 4;
    atomicAdd(&sp[0], a0); atomicAdd(&sp[1], a1);
    atomicAdd(&sp[2], a2); atomicAdd(&sp[3], a3);
}

// ---------------------------------------------------------------------------
// P1/P2: warp-autonomous routing pass. Warp = (b, 32 i's). Lane owns
// oA=2*lane, oB=2*lane+1 -> each lane reads its 128B contiguous row pair.
// Softmax over 64 o's via shuffles; S in regs; atomicAdd tail.
// ---------------------------------------------------------------------------
__global__ void __launch_bounds__(128) p1_kernel(int pass) {
    const int gw = blockIdx.x * (blockDim.x >> 5) + (threadIdx.x >> 5);
    const int lane = threadIdx.x & 31;
    const int b = gw >> 6;
    const int i0 = (gw & 63) * 32;
    float* Sout = (pass == 1) ? g_S1 : g_S2;

    const int oA = 2 * lane;

    float va[VO], vb[VO];
    {
        const float4* vp = (const float4*)(g_Vacc + (size_t)(b * O + oA) * VO);
#pragma unroll
        for (int j = 0; j < 8; j++) {
            float4 t4 = vp[j];
            va[4 * j + 0] = t4.x; va[4 * j + 1] = t4.y; va[4 * j + 2] = t4.z; va[4 * j + 3] = t4.w;
            float4 s4 = vp[j + 8];
            vb[4 * j + 0] = s4.x; vb[4 * j + 1] = s4.y; vb[4 * j + 2] = s4.z; vb[4 * j + 3] = s4.w;
        }
    }

    float sa[VO], sb[VO];
#pragma unroll
    for (int v = 0; v < VO; v++) { sa[v] = 0.f; sb[v] = 0.f; }

    for (int ic = 0; ic < 32; ic++) {
        const int i = i0 + ic;
        const uint4* up = (const uint4*)(g_uhat + (((size_t)b * I + i) * O + oA) * VO);
        uint4 h0 = __ldcs(up + 0);
        uint4 h1 = __ldcs(up + 1);
        uint4 h2 = __ldcs(up + 2);
        uint4 h3 = __ldcs(up + 3);
        uint4 g0 = __ldcs(up + 4);
        uint4 g1 = __ldcs(up + 5);
        uint4 g2 = __ldcs(up + 6);
        uint4 g3 = __ldcs(up + 7);

        unsigned int r0[16] = {h0.x, h0.y, h0.z, h0.w, h1.x, h1.y, h1.z, h1.w,
                               h2.x, h2.y, h2.z, h2.w, h3.x, h3.y, h3.z, h3.w};
        unsigned int r1[16] = {g0.x, g0.y, g0.z, g0.w, g1.x, g1.y, g1.z, g1.w,
                               g2.x, g2.y, g2.z, g2.w, g3.x, g3.y, g3.z, g3.w};

        float d0 = 0.f, d1 = 0.f;
#pragma unroll
        for (int j = 0; j < 16; j++) {
            float2 f0 = __half22float2(*(const __half2*)&r0[j]);
            d0 = fmaf(f0.x, va[2 * j + 0], d0);
            d0 = fmaf(f0.y, va[2 * j + 1], d0);
            float2 f1 = __half22float2(*(const __half2*)&r1[j]);
            d1 = fmaf(f1.x, vb[2 * j + 0], d1);
            d1 = fmaf(f1.y, vb[2 * j + 1], d1);
        }

        float m = fmaxf(d0, d1);
#pragma unroll
        for (int off = 16; off; off >>= 1)
            m = fmaxf(m, __shfl_xor_sync(0xffffffffu, m, off));
        float e0 = __expf(d0 - m);
        float e1 = __expf(d1 - m);
        float es = e0 + e1;
#pragma unroll
        for (int off = 16; off; off >>= 1)
            es += __shfl_xor_sync(0xffffffffu, es, off);
        float inv = __frcp_rn(es);
        float c0 = e0 * inv;
        float c1 = e1 * inv;

#pragma unroll
        for (int j = 0; j < 16; j++) {
            float2 f0 = __half22float2(*(const __half2*)&r0[j]);
            sa[2 * j + 0] = fmaf(c0, f0.x, sa[2 * j + 0]);
            sa[2 * j + 1] = fmaf(c0, f0.y, sa[2 * j + 1]);
            float2 f1 = __half22float2(*(const __half2*)&r1[j]);
            sb[2 * j + 0] = fmaf(c1, f1.x, sb[2 * j + 0]);
            sb[2 * j + 1] = fmaf(c1, f1.y, sb[2 * j + 1]);
        }
    }

    float* sp0 = Sout + (size_t)(b * O + oA) * VO;
#pragma unroll
    for (int v = 0; v < VO; v++) {
        atomicAdd(&sp0[v], sa[v]);
        atomicAdd(&sp0[VO + v], sb[v]);
    }
}

// ---------------------------------------------------------------------------
// Squash. which==0: v0=squash(S0/64), Vacc=v0.
//         which==1: v1=squash(S1),   Vacc+=v1.
//         which==2: out=squash(S2).
// ---------------------------------------------------------------------------
__global__ void kv_kernel(int which, float* __restrict__ out) {
    int wid = threadIdx.x >> 5;
    int lane = threadIdx.x & 31;
    int pair = blockIdx.x * (blockDim.x >> 5) + wid;
    if (pair >= B * O) return;
    int idx = pair * VO + lane;

    float s;
    if (which == 0)      s = g_S0[idx] * (1.0f / (float)O);
    else if (which == 1) s = g_S1[idx];
    else                 s = g_S2[idx];

    float sq = s * s;
#pragma unroll
    for (int off = 16; off; off >>= 1)
        sq += __shfl_xor_sync(0xffffffffu, sq, off);

    float scale = (sq / (1.0f + sq)) * rsqrtf(sq + 1e-8f);
    float v = s * scale;

    if (which == 0)      g_Vacc[idx] = v;
    else if (which == 1) g_Vacc[idx] += v;
    else                 out[idx] = v;
}

// ---------------------------------------------------------------------------
extern "C" void kernel_launch(void* const* d_in, const int* in_sizes, int n_in,
                              void* d_out, int out_size) {
    const float* x;
    const float* W;
    if (in_sizes[0] == B * I * VI) {
        x = (const float*)d_in[0];
        W = (const float*)d_in[1];
    } else {
        x = (const float*)d_in[1];
        W = (const float*)d_in[0];
    }
    float* out = (float*)d_out;

    zero_kernel<<<(B * O * VO + 255) / 256, 256>>>();

    // P0: u_hat (fp16)
    p0_kernel<<<dim3(I, O / 16), 256>>>(W, x);

    // Iteration 0 (uniform coupling): S0 = sum_i u_hat
    s0_kernel<<<256, 256>>>();
    kv_kernel<<<64, 1024>>>(0, out);   // v0 = squash(S0/64); Vacc = v0

    // Iteration 1: logits = u_hat . v0
    p1_kernel<<<512, 128>>>(1);
    kv_kernel<<<64, 1024>>>(1, out);   // v1 = squash(S1); Vacc = v0 + v1

    // Iteration 2: logits = u_hat . (v0 + v1)
    p1_kernel<<<512, 128>>>(2);
    kv_kernel<<<64, 1024>>>(2, out);   // out = squash(S2)
}

// round 9
// speedup vs baseline: 1.0195x; 1.0195x over previous
#include <cuda_runtime.h>
#include <cuda_fp16.h>
#include <math.h>

// Problem constants
#define B  32
#define O  64
#define I  2048
#define VO 32
#define VI 16

typedef unsigned long long u64;

// Scratch (device globals: no allocation allowed)
__device__ __half g_uhat[(size_t)B * I * O * VO];  // [b][i][o][v], fp16, 256 MB
__device__ float g_S0[B * O * VO];
__device__ float g_S1[B * O * VO];
__device__ float g_S2[B * O * VO];
__device__ float g_Vacc[B * O * VO];               // v0, then v0+v1

// ---------------------------------------------------------------------------
// helpers
// ---------------------------------------------------------------------------
__device__ __forceinline__ unsigned int smem_u32(const void* p) {
    return (unsigned int)__cvta_generic_to_shared(p);
}
__device__ __forceinline__ void mma_16816(float* d, const unsigned int* a,
                                          const unsigned int* b) {
    asm volatile(
        "mma.sync.aligned.m16n8k16.row.col.f32.f16.f16.f32 "
        "{%0,%1,%2,%3},{%4,%5,%6,%7},{%8,%9},{%0,%1,%2,%3};"
        : "+f"(d[0]), "+f"(d[1]), "+f"(d[2]), "+f"(d[3])
        : "r"(a[0]), "r"(a[1]), "r"(a[2]), "r"(a[3]), "r"(b[0]), "r"(b[1]));
}
// NON-trans ldmatrix: SMEM rows are n (=v), cols are k (=u) -> B fragment
__device__ __forceinline__ void ldmx2(unsigned int& b0, unsigned int& b1,
                                      unsigned int saddr) {
    asm volatile("ldmatrix.sync.aligned.m8n8.x2.shared.b16 {%0,%1},[%2];"
                 : "=r"(b0), "=r"(b1) : "r"(saddr));
}
__device__ __forceinline__ void stg_cs32(void* p, unsigned int v) {
    asm volatile("st.global.cs.b32 [%0],%1;" :: "l"(p), "r"(v) : "memory");
}
__device__ __forceinline__ unsigned int pack_h(float a, float b) {
    __half2 p = __halves2half2(__float2half_rn(a), __float2half_rn(b));
    return *(unsigned int*)&p;
}
__device__ __forceinline__ unsigned int pack_l(float a, float b, unsigned int hp) {
    float2 hf = __half22float2(*(__half2*)&hp);
    __half2 p = __halves2half2(__float2half_rn(a - hf.x), __float2half_rn(b - hf.y));
    return *(unsigned int*)&p;
}

// ---------------------------------------------------------------------------
// Zero the atomic accumulators (graph replays reuse scratch)
// ---------------------------------------------------------------------------
__global__ void zero_kernel() {
    int idx = blockIdx.x * blockDim.x + threadIdx.x;
    if (idx < B * O * VO) {
        g_S0[idx] = 0.0f;
        g_S1[idx] = 0.0f;
        g_S2[idx] = 0.0f;
    }
}

// ---------------------------------------------------------------------------
// P0 (tensor cores, mma.sync): per CTA one (i, 4-o tile) GEMM
//   D[b][ (o,v) ] = sum_u x[b][u] * W[(o,v)][u]
// M=32 (b) on the MMA M side so each thread's (c0,c1) pair is adjacent in v
// -> direct half2 global stores, no SMEM transpose.
// A = x: fragments built in registers from SMEM floats (hi/lo fp16 split).
// B = W: fp16 hi/lo tiles in SMEM (rows = (o,v), cols = 16 u; pad to 24
// halves), loaded via NON-trans ldmatrix.x2 (rows=n, cols=k -> B fragment).
// 3-term split (xh*Wh + xl*Wh + xh*Wl) ~ fp32 accuracy.
// ---------------------------------------------------------------------------
__global__ void __launch_bounds__(128) p0_mma(const float* __restrict__ W,
                                              const float* __restrict__ x) {
    __shared__ __half Wh[128 * 24];   // 6 KB
    __shared__ __half Wl[128 * 24];   // 6 KB
    __shared__ float  Xs[32 * 16];    // 2 KB

    const int i   = blockIdx.x;
    const int o0  = blockIdx.y * 4;
    const int tid = threadIdx.x;
    const int wid = tid >> 5;
    const int lane = tid & 31;

    // Stage W row m = tid (o = o0+wid, v = lane): 16 floats -> hi/lo halves
    {
        const float* wrow = W + (((size_t)(o0 + wid) * I + i) * VO + lane) * VI;
        unsigned int hh[8], ll[8];
#pragma unroll
        for (int q = 0; q < 4; q++) {
            float4 f = *(const float4*)(wrow + q * 4);
            float fv[4] = {f.x, f.y, f.z, f.w};
#pragma unroll
            for (int j = 0; j < 2; j++) {
                unsigned int h = pack_h(fv[2 * j], fv[2 * j + 1]);
                hh[q * 2 + j] = h;
                ll[q * 2 + j] = pack_l(fv[2 * j], fv[2 * j + 1], h);
            }
        }
        uint4* dh = (uint4*)&Wh[tid * 24];
        dh[0] = make_uint4(hh[0], hh[1], hh[2], hh[3]);
        dh[1] = make_uint4(hh[4], hh[5], hh[6], hh[7]);
        uint4* dl = (uint4*)&Wl[tid * 24];
        dl[0] = make_uint4(ll[0], ll[1], ll[2], ll[3]);
        dl[1] = make_uint4(ll[4], ll[5], ll[6], ll[7]);
    }
    // Stage x: 128 float4 = x[b = t>>2][uquad = t&3]
    {
        int b = tid >> 2, q = tid & 3;
        *(float4*)&Xs[b * 16 + q * 4] =
            *(const float4*)(x + ((size_t)b * I + i) * VI + q * 4);
    }
    __syncthreads();

    // A fragments (x, hi/lo) in registers. m16n8k16 A row-major mapping:
    // a0 = A[g][2c,2c+1], a1 = A[g+8][..], a2 = A[g][2c+8,..], a3 = A[g+8][2c+8,..]
    const int gid = lane >> 2, tig = lane & 3;
    unsigned int Ah[2][4], Al[2][4];
#pragma unroll
    for (int mt = 0; mt < 2; mt++) {
        int r0 = gid + mt * 16, r1 = r0 + 8;
        float2 x00 = *(float2*)&Xs[r0 * 16 + 2 * tig];
        float2 x01 = *(float2*)&Xs[r0 * 16 + 2 * tig + 8];
        float2 x10 = *(float2*)&Xs[r1 * 16 + 2 * tig];
        float2 x11 = *(float2*)&Xs[r1 * 16 + 2 * tig + 8];
        Ah[mt][0] = pack_h(x00.x, x00.y);
        Ah[mt][1] = pack_h(x10.x, x10.y);
        Ah[mt][2] = pack_h(x01.x, x01.y);
        Ah[mt][3] = pack_h(x11.x, x11.y);
        Al[mt][0] = pack_l(x00.x, x00.y, Ah[mt][0]);
        Al[mt][1] = pack_l(x10.x, x10.y, Ah[mt][1]);
        Al[mt][2] = pack_l(x01.x, x01.y, Ah[mt][2]);
        Al[mt][3] = pack_l(x11.x, x11.y, Ah[mt][3]);
    }

    const int o = o0 + wid;
    const int lr = lane & 7, sel = (lane >> 3) & 1;

#pragma unroll
    for (int nt = 0; nt < 4; nt++) {
        // B tile (x2): matrix0 = rows n = wid*32+nt*8+(0..7), k 0..7 (lanes
        // 0-7, sel=0); matrix1 = same rows, k 8..15 (lanes 8-15, sel=1).
        unsigned int bh[2], bl[2];
        ldmx2(bh[0], bh[1],
              smem_u32(&Wh[(wid * 32 + nt * 8 + lr) * 24 + sel * 8]));
        ldmx2(bl[0], bl[1],
              smem_u32(&Wl[(wid * 32 + nt * 8 + lr) * 24 + sel * 8]));
#pragma unroll
        for (int mt = 0; mt < 2; mt++) {
            float d[4] = {0.f, 0.f, 0.f, 0.f};
            mma_16816(d, Ah[mt], bh);
            mma_16816(d, Al[mt], bh);
            mma_16816(d, Ah[mt], bl);

            // D[m=b][n=v]: c0,c1 -> b=gid+mt*16, v=2tig+nt*8 (+1);
            //              c2,c3 -> b+8, same v pair
            int v  = 2 * tig + nt * 8;
            int b0r = gid + mt * 16;
            size_t h0 = (((size_t)b0r * I + i) * O + o) * VO + v;
            size_t h1 = (((size_t)(b0r + 8) * I + i) * O + o) * VO + v;
            stg_cs32(g_uhat + h0, pack_h(d[0], d[1]));
            stg_cs32(g_uhat + h1, pack_h(d[2], d[3]));
        }
    }
}

// ---------------------------------------------------------------------------
// S0 pass: S0[b,o,v] = sum_i u_hat. Thread owns (b,o,q,c): q = uint2 column
// (4 v's), c one of 4 i-chunks; atomicAdd tail into zeroed S0. 65536 threads.
// ---------------------------------------------------------------------------
__global__ void __launch_bounds__(256) s0_kernel() {
    int t = blockIdx.x * 256 + threadIdx.x;   // 0 .. 65535
    int q = t & 7;
    int o = (t >> 3) & 63;
    int c = (t >> 9) & 3;
    int b = t >> 11;

    const uint2* up = (const uint2*)g_uhat;
    size_t base = (((size_t)b * I + (size_t)c * 512) * O + (size_t)o) * 8 + q;
    const size_t istride = (size_t)O * 8;

    float a0 = 0.f, a1 = 0.f, a2 = 0.f, a3 = 0.f;
#pragma unroll 8
    for (int i = 0; i < 512; i++) {
        uint2 h = __ldcs(&up[base + (size_t)i * istride]);
        float2 f0 = __half22float2(*(const __half2*)&h.x);
        float2 f1 = __half22float2(*(const __half2*)&h.y);
        a0 += f0.x; a1 += f0.y; a2 += f1.x; a3 += f1.y;
    }
    float* sp = g_S0 + (size_t)(b * O + o) * VO + q * 4;
    atomicAdd(&sp[0], a0); atomicAdd(&sp[1], a1);
    atomicAdd(&sp[2], a2); atomicAdd(&sp[3], a3);
}

// ---------------------------------------------------------------------------
// P1/P2: warp-autonomous routing pass. Warp = (b, 32 i's). Lane owns
// oA=2*lane, oB=2*lane+1 -> each lane reads its 128B contiguous row pair.
// Softmax over 64 o's via shuffles; S in regs; atomicAdd tail.
// ---------------------------------------------------------------------------
__global__ void __launch_bounds__(128) p1_kernel(int pass) {
    const int gw = blockIdx.x * (blockDim.x >> 5) + (threadIdx.x >> 5);
    const int lane = threadIdx.x & 31;
    const int b = gw >> 6;
    const int i0 = (gw & 63) * 32;
    float* Sout = (pass == 1) ? g_S1 : g_S2;

    const int oA = 2 * lane;

    float va[VO], vb[VO];
    {
        const float4* vp = (const float4*)(g_Vacc + (size_t)(b * O + oA) * VO);
#pragma unroll
        for (int j = 0; j < 8; j++) {
            float4 t4 = vp[j];
            va[4 * j + 0] = t4.x; va[4 * j + 1] = t4.y; va[4 * j + 2] = t4.z; va[4 * j + 3] = t4.w;
            float4 s4 = vp[j + 8];
            vb[4 * j + 0] = s4.x; vb[4 * j + 1] = s4.y; vb[4 * j + 2] = s4.z; vb[4 * j + 3] = s4.w;
        }
    }

    float sa[VO], sb[VO];
#pragma unroll
    for (int v = 0; v < VO; v++) { sa[v] = 0.f; sb[v] = 0.f; }

    for (int ic = 0; ic < 32; ic++) {
        const int i = i0 + ic;
        const uint4* up = (const uint4*)(g_uhat + (((size_t)b * I + i) * O + oA) * VO);
        uint4 h0 = __ldcs(up + 0);
        uint4 h1 = __ldcs(up + 1);
        uint4 h2 = __ldcs(up + 2);
        uint4 h3 = __ldcs(up + 3);
        uint4 g0 = __ldcs(up + 4);
        uint4 g1 = __ldcs(up + 5);
        uint4 g2 = __ldcs(up + 6);
        uint4 g3 = __ldcs(up + 7);

        unsigned int r0[16] = {h0.x, h0.y, h0.z, h0.w, h1.x, h1.y, h1.z, h1.w,
                               h2.x, h2.y, h2.z, h2.w, h3.x, h3.y, h3.z, h3.w};
        unsigned int r1[16] = {g0.x, g0.y, g0.z, g0.w, g1.x, g1.y, g1.z, g1.w,
                               g2.x, g2.y, g2.z, g2.w, g3.x, g3.y, g3.z, g3.w};

        float d0 = 0.f, d1 = 0.f;
#pragma unroll
        for (int j = 0; j < 16; j++) {
            float2 f0 = __half22float2(*(const __half2*)&r0[j]);
            d0 = fmaf(f0.x, va[2 * j + 0], d0);
            d0 = fmaf(f0.y, va[2 * j + 1], d0);
            float2 f1 = __half22float2(*(const __half2*)&r1[j]);
            d1 = fmaf(f1.x, vb[2 * j + 0], d1);
            d1 = fmaf(f1.y, vb[2 * j + 1], d1);
        }

        float m = fmaxf(d0, d1);
#pragma unroll
        for (int off = 16; off; off >>= 1)
            m = fmaxf(m, __shfl_xor_sync(0xffffffffu, m, off));
        float e0 = __expf(d0 - m);
        float e1 = __expf(d1 - m);
        float es = e0 + e1;
#pragma unroll
        for (int off = 16; off; off >>= 1)
            es += __shfl_xor_sync(0xffffffffu, es, off);
        float inv = __frcp_rn(es);
        float c0 = e0 * inv;
        float c1 = e1 * inv;

#pragma unroll
        for (int j = 0; j < 16; j++) {
            float2 f0 = __half22float2(*(const __half2*)&r0[j]);
            sa[2 * j + 0] = fmaf(c0, f0.x, sa[2 * j + 0]);
            sa[2 * j + 1] = fmaf(c0, f0.y, sa[2 * j + 1]);
            float2 f1 = __half22float2(*(const __half2*)&r1[j]);
            sb[2 * j + 0] = fmaf(c1, f1.x, sb[2 * j + 0]);
            sb[2 * j + 1] = fmaf(c1, f1.y, sb[2 * j + 1]);
        }
    }

    float* sp0 = Sout + (size_t)(b * O + oA) * VO;
#pragma unroll
    for (int v = 0; v < VO; v++) {
        atomicAdd(&sp0[v], sa[v]);
        atomicAdd(&sp0[VO + v], sb[v]);
    }
}

// ---------------------------------------------------------------------------
// Squash. which==0: v0=squash(S0/64), Vacc=v0.
//         which==1: v1=squash(S1),   Vacc+=v1.
//         which==2: out=squash(S2).
// ---------------------------------------------------------------------------
__global__ void kv_kernel(int which, float* __restrict__ out) {
    int wid = threadIdx.x >> 5;
    int lane = threadIdx.x & 31;
    int pair = blockIdx.x * (blockDim.x >> 5) + wid;
    if (pair >= B * O) return;
    int idx = pair * VO + lane;

    float s;
    if (which == 0)      s = g_S0[idx] * (1.0f / (float)O);
    else if (which == 1) s = g_S1[idx];
    else                 s = g_S2[idx];

    float sq = s * s;
#pragma unroll
    for (int off = 16; off; off >>= 1)
        sq += __shfl_xor_sync(0xffffffffu, sq, off);

    float scale = (sq / (1.0f + sq)) * rsqrtf(sq + 1e-8f);
    float v = s * scale;

    if (which == 0)      g_Vacc[idx] = v;
    else if (which == 1) g_Vacc[idx] += v;
    else                 out[idx] = v;
}

// ---------------------------------------------------------------------------
extern "C" void kernel_launch(void* const* d_in, const int* in_sizes, int n_in,
                              void* d_out, int out_size) {
    const float* x;
    const float* W;
    if (in_sizes[0] == B * I * VI) {
        x = (const float*)d_in[0];
        W = (const float*)d_in[1];
    } else {
        x = (const float*)d_in[1];
        W = (const float*)d_in[0];
    }
    float* out = (float*)d_out;

    zero_kernel<<<(B * O * VO + 255) / 256, 256>>>();

    // P0: u_hat (fp16) via mma.sync tensor cores, hi/lo split
    p0_mma<<<dim3(I, O / 4), 128>>>(W, x);

    // Iteration 0 (uniform coupling): S0 = sum_i u_hat
    s0_kernel<<<256, 256>>>();
    kv_kernel<<<64, 1024>>>(0, out);   // v0 = squash(S0/64); Vacc = v0

    // Iteration 1: logits = u_hat . v0
    p1_kernel<<<512, 128>>>(1);
    kv_kernel<<<64, 1024>>>(1, out);   // v1 = squash(S1); Vacc = v0 + v1

    // Iteration 2: logits = u_hat . (v0 + v1)
    p1_kernel<<<512, 128>>>(2);
    kv_kernel<<<64, 1024>>>(2, out);   // out = squash(S2)
}

// round 10
// speedup vs baseline: 1.4588x; 1.4309x over previous
#include <cuda_runtime.h>
#include <cuda_fp16.h>
#include <math.h>

// Problem constants
#define B  32
#define O  64
#define I  2048
#define VO 32
#define VI 16

#define ITER 8            // i's per p0 CTA

typedef unsigned long long u64;

// Scratch (device globals: no allocation allowed)
__device__ __half g_uhat[(size_t)B * I * O * VO];  // [b][i][o][v], fp16, 256 MB
__device__ float g_S0[B * O * VO];
__device__ float g_S1[B * O * VO];
__device__ float g_S2[B * O * VO];
__device__ float g_Vacc[B * O * VO];               // v0, then v0+v1

// ---------------------------------------------------------------------------
// helpers
// ---------------------------------------------------------------------------
__device__ __forceinline__ unsigned int smem_u32(const void* p) {
    return (unsigned int)__cvta_generic_to_shared(p);
}
__device__ __forceinline__ void mma_16816(float* d, const unsigned int* a,
                                          const unsigned int* b) {
    asm volatile(
        "mma.sync.aligned.m16n8k16.row.col.f32.f16.f16.f32 "
        "{%0,%1,%2,%3},{%4,%5,%6,%7},{%8,%9},{%0,%1,%2,%3};"
        : "+f"(d[0]), "+f"(d[1]), "+f"(d[2]), "+f"(d[3])
        : "r"(a[0]), "r"(a[1]), "r"(a[2]), "r"(a[3]), "r"(b[0]), "r"(b[1]));
}
// NON-trans ldmatrix: SMEM rows are n (=v), cols are k (=u) -> B fragment
__device__ __forceinline__ void ldmx2(unsigned int& b0, unsigned int& b1,
                                      unsigned int saddr) {
    asm volatile("ldmatrix.sync.aligned.m8n8.x2.shared.b16 {%0,%1},[%2];"
                 : "=r"(b0), "=r"(b1) : "r"(saddr));
}
__device__ __forceinline__ unsigned int pack_h(float a, float b) {
    __half2 p = __halves2half2(__float2half_rn(a), __float2half_rn(b));
    return *(unsigned int*)&p;
}
__device__ __forceinline__ unsigned int pack_l(float a, float b, unsigned int hp) {
    float2 hf = __half22float2(*(__half2*)&hp);
    __half2 p = __halves2half2(__float2half_rn(a - hf.x), __float2half_rn(b - hf.y));
    return *(unsigned int*)&p;
}

// ---------------------------------------------------------------------------
// Zero the atomic accumulators (graph replays reuse scratch)
// ---------------------------------------------------------------------------
__global__ void zero_kernel() {
    int idx = blockIdx.x * blockDim.x + threadIdx.x;
    if (idx < B * O * VO) {
        g_S0[idx] = 0.0f;
        g_S1[idx] = 0.0f;
        g_S2[idx] = 0.0f;
    }
}

// ---------------------------------------------------------------------------
// P0 v2 (tensor cores, mma.sync, amortized):
// Grid (I/ITER, O/8), 256 threads = 8 warps; warp w owns o = o0+w.
// Loop over ITER i's with register-prefetch of next-i W/x LDGs.
// Per i: D[b=32][(o,v)] = x . W^T via m16n8k16, 3-term fp16 hi/lo split.
// Epilogue through SMEM Dout -> fully coalesced 16B u_hat stores.
// ---------------------------------------------------------------------------
__global__ void __launch_bounds__(256) p0_mma(const float* __restrict__ W,
                                              const float* __restrict__ x) {
    __shared__ __half Whs[8 * 32 * 24];  // 12 KB  per-warp W-hi tile
    __shared__ __half Wls[8 * 32 * 24];  // 12 KB  per-warp W-lo tile
    __shared__ float  Xs[32 * 24];       //  3 KB  x fp32 (padded rows)
    __shared__ __half Dout[32 * 264];    // 16.5 KB output staging (padded)

    const int i0  = blockIdx.x * ITER;
    const int o0  = blockIdx.y * 8;
    const int tid = threadIdx.x;
    const int wid = tid >> 5;
    const int lane = tid & 31;

    const int gid = lane >> 2, tig = lane & 3;
    const int lr = lane & 7, sel = (lane >> 3) & 1;

    // W row base for this warp's o (2048 floats per i, contiguous)
    const float4* wbase = (const float4*)(W + ((size_t)(o0 + wid) * I + i0) * 512);
    const int xb = tid >> 2, xq = tid & 3;   // threads<128 stage x

    // ---- prologue: prefetch i0 ----
    float4 w4[4];
#pragma unroll
    for (int j = 0; j < 4; j++) w4[j] = wbase[j * 32 + lane];
    float4 x4;
    if (tid < 128)
        x4 = *(const float4*)(x + ((size_t)xb * I + i0) * VI + xq * 4);

    for (int it = 0; it < ITER; it++) {
        const int i = i0 + it;

        // ---- stage from prefetch regs ----
#pragma unroll
        for (int j = 0; j < 4; j++) {
            int c = j * 32 + lane;
            int v = c >> 2, q = c & 3;
            unsigned int h0 = pack_h(w4[j].x, w4[j].y);
            unsigned int h1 = pack_h(w4[j].z, w4[j].w);
            unsigned int l0 = pack_l(w4[j].x, w4[j].y, h0);
            unsigned int l1 = pack_l(w4[j].z, w4[j].w, h1);
            *(uint2*)&Whs[(wid * 32 + v) * 24 + q * 4] = make_uint2(h0, h1);
            *(uint2*)&Wls[(wid * 32 + v) * 24 + q * 4] = make_uint2(l0, l1);
        }
        if (tid < 128)
            *(float4*)&Xs[xb * 24 + xq * 4] = x4;

        // ---- prefetch next i ----
        if (it + 1 < ITER) {
            const float4* wb2 = wbase + (size_t)(it + 1) * 128;
#pragma unroll
            for (int j = 0; j < 4; j++) w4[j] = wb2[j * 32 + lane];
            if (tid < 128)
                x4 = *(const float4*)(x + ((size_t)xb * I + (i + 1)) * VI + xq * 4);
        }
        __syncthreads();   // staging visible (also: prev Dout fully consumed)

        // ---- A fragments (proven R9 mapping) ----
        unsigned int Ah[2][4], Al[2][4];
#pragma unroll
        for (int mt = 0; mt < 2; mt++) {
            int r0 = gid + mt * 16, r1 = r0 + 8;
            float2 x00 = *(float2*)&Xs[r0 * 24 + 2 * tig];
            float2 x01 = *(float2*)&Xs[r0 * 24 + 2 * tig + 8];
            float2 x10 = *(float2*)&Xs[r1 * 24 + 2 * tig];
            float2 x11 = *(float2*)&Xs[r1 * 24 + 2 * tig + 8];
            Ah[mt][0] = pack_h(x00.x, x00.y);
            Ah[mt][1] = pack_h(x10.x, x10.y);
            Ah[mt][2] = pack_h(x01.x, x01.y);
            Ah[mt][3] = pack_h(x11.x, x11.y);
            Al[mt][0] = pack_l(x00.x, x00.y, Ah[mt][0]);
            Al[mt][1] = pack_l(x10.x, x10.y, Ah[mt][1]);
            Al[mt][2] = pack_l(x01.x, x01.y, Ah[mt][2]);
            Al[mt][3] = pack_l(x11.x, x11.y, Ah[mt][3]);
        }

        // ---- MMA + epilogue STS into Dout ----
#pragma unroll
        for (int nt = 0; nt < 4; nt++) {
            unsigned int bh[2], bl[2];
            ldmx2(bh[0], bh[1],
                  smem_u32(&Whs[(wid * 32 + nt * 8 + lr) * 24 + sel * 8]));
            ldmx2(bl[0], bl[1],
                  smem_u32(&Wls[(wid * 32 + nt * 8 + lr) * 24 + sel * 8]));
#pragma unroll
            for (int mt = 0; mt < 2; mt++) {
                float d[4] = {0.f, 0.f, 0.f, 0.f};
                mma_16816(d, Ah[mt], bh);
                mma_16816(d, Al[mt], bh);
                mma_16816(d, Ah[mt], bl);

                int v  = 2 * tig + nt * 8;
                int b0 = gid + mt * 16;
                // Dout[b][wid*32+v], row pitch 264 halves (conflict-free)
                *(unsigned int*)&Dout[b0 * 264 + wid * 32 + v] = pack_h(d[0], d[1]);
                *(unsigned int*)&Dout[(b0 + 8) * 264 + wid * 32 + v] = pack_h(d[2], d[3]);
            }
        }
        __syncthreads();   // Dout complete

        // ---- coalesced store: warp = one b's contiguous 512B ----
#pragma unroll
        for (int j = 0; j < 4; j++) {
            int c = j * 256 + tid;
            int b = c >> 5, k = c & 31;
            uint4 val = *(uint4*)((char*)Dout + b * 528 + k * 16);
            __half* dst = g_uhat + (((size_t)b * I + i) * O + o0) * VO + k * 8;
            __stcs((uint4*)dst, val);
        }
        // next iteration's __syncthreads() protects Dout reuse
    }
}

// ---------------------------------------------------------------------------
// S0 pass: S0[b,o,v] = sum_i u_hat. Thread owns (b,o,q,c): q = uint2 column
// (4 v's), c one of 4 i-chunks; atomicAdd tail into zeroed S0. 65536 threads.
// ---------------------------------------------------------------------------
__global__ void __launch_bounds__(256) s0_kernel() {
    int t = blockIdx.x * 256 + threadIdx.x;   // 0 .. 65535
    int q = t & 7;
    int o = (t >> 3) & 63;
    int c = (t >> 9) & 3;
    int b = t >> 11;

    const uint2* up = (const uint2*)g_uhat;
    size_t base = (((size_t)b * I + (size_t)c * 512) * O + (size_t)o) * 8 + q;
    const size_t istride = (size_t)O * 8;

    float a0 = 0.f, a1 = 0.f, a2 = 0.f, a3 = 0.f;
#pragma unroll 8
    for (int i = 0; i < 512; i++) {
        uint2 h = __ldcs(&up[base + (size_t)i * istride]);
        float2 f0 = __half22float2(*(const __half2*)&h.x);
        float2 f1 = __half22float2(*(const __half2*)&h.y);
        a0 += f0.x; a1 += f0.y; a2 += f1.x; a3 += f1.y;
    }
    float* sp = g_S0 + (size_t)(b * O + o) * VO + q * 4;
    atomicAdd(&sp[0], a0); atomicAdd(&sp[1], a1);
    atomicAdd(&sp[2], a2); atomicAdd(&sp[3], a3);
}

// ---------------------------------------------------------------------------
// P1/P2: warp-autonomous routing pass. Warp = (b, 32 i's). Lane owns
// oA=2*lane, oB=2*lane+1 -> each lane reads its 128B contiguous row pair.
// Softmax over 64 o's via shuffles; S in regs; atomicAdd tail.
// ---------------------------------------------------------------------------
__global__ void __launch_bounds__(128) p1_kernel(int pass) {
    const int gw = blockIdx.x * (blockDim.x >> 5) + (threadIdx.x >> 5);
    const int lane = threadIdx.x & 31;
    const int b = gw >> 6;
    const int i0 = (gw & 63) * 32;
    float* Sout = (pass == 1) ? g_S1 : g_S2;

    const int oA = 2 * lane;

    float va[VO], vb[VO];
    {
        const float4* vp = (const float4*)(g_Vacc + (size_t)(b * O + oA) * VO);
#pragma unroll
        for (int j = 0; j < 8; j++) {
            float4 t4 = vp[j];
            va[4 * j + 0] = t4.x; va[4 * j + 1] = t4.y; va[4 * j + 2] = t4.z; va[4 * j + 3] = t4.w;
            float4 s4 = vp[j + 8];
            vb[4 * j + 0] = s4.x; vb[4 * j + 1] = s4.y; vb[4 * j + 2] = s4.z; vb[4 * j + 3] = s4.w;
        }
    }

    float sa[VO], sb[VO];
#pragma unroll
    for (int v = 0; v < VO; v++) { sa[v] = 0.f; sb[v] = 0.f; }

    for (int ic = 0; ic < 32; ic++) {
        const int i = i0 + ic;
        const uint4* up = (const uint4*)(g_uhat + (((size_t)b * I + i) * O + oA) * VO);
        uint4 h0 = __ldcs(up + 0);
        uint4 h1 = __ldcs(up + 1);
        uint4 h2 = __ldcs(up + 2);
        uint4 h3 = __ldcs(up + 3);
        uint4 g0 = __ldcs(up + 4);
        uint4 g1 = __ldcs(up + 5);
        uint4 g2 = __ldcs(up + 6);
        uint4 g3 = __ldcs(up + 7);

        unsigned int r0[16] = {h0.x, h0.y, h0.z, h0.w, h1.x, h1.y, h1.z, h1.w,
                               h2.x, h2.y, h2.z, h2.w, h3.x, h3.y, h3.z, h3.w};
        unsigned int r1[16] = {g0.x, g0.y, g0.z, g0.w, g1.x, g1.y, g1.z, g1.w,
                               g2.x, g2.y, g2.z, g2.w, g3.x, g3.y, g3.z, g3.w};

        float d0 = 0.f, d1 = 0.f;
#pragma unroll
        for (int j = 0; j < 16; j++) {
            float2 f0 = __half22float2(*(const __half2*)&r0[j]);
            d0 = fmaf(f0.x, va[2 * j + 0], d0);
            d0 = fmaf(f0.y, va[2 * j + 1], d0);
            float2 f1 = __half22float2(*(const __half2*)&r1[j]);
            d1 = fmaf(f1.x, vb[2 * j + 0], d1);
            d1 = fmaf(f1.y, vb[2 * j + 1], d1);
        }

        float m = fmaxf(d0, d1);
#pragma unroll
        for (int off = 16; off; off >>= 1)
            m = fmaxf(m, __shfl_xor_sync(0xffffffffu, m, off));
        float e0 = __expf(d0 - m);
        float e1 = __expf(d1 - m);
        float es = e0 + e1;
#pragma unroll
        for (int off = 16; off; off >>= 1)
            es += __shfl_xor_sync(0xffffffffu, es, off);
        float inv = __frcp_rn(es);
        float c0 = e0 * inv;
        float c1 = e1 * inv;

#pragma unroll
        for (int j = 0; j < 16; j++) {
            float2 f0 = __half22float2(*(const __half2*)&r0[j]);
            sa[2 * j + 0] = fmaf(c0, f0.x, sa[2 * j + 0]);
            sa[2 * j + 1] = fmaf(c0, f0.y, sa[2 * j + 1]);
            float2 f1 = __half22float2(*(const __half2*)&r1[j]);
            sb[2 * j + 0] = fmaf(c1, f1.x, sb[2 * j + 0]);
            sb[2 * j + 1] = fmaf(c1, f1.y, sb[2 * j + 1]);
        }
    }

    float* sp0 = Sout + (size_t)(b * O + oA) * VO;
#pragma unroll
    for (int v = 0; v < VO; v++) {
        atomicAdd(&sp0[v], sa[v]);
        atomicAdd(&sp0[VO + v], sb[v]);
    }
}

// ---------------------------------------------------------------------------
// Squash. which==0: v0=squash(S0/64), Vacc=v0.
//         which==1: v1=squash(S1),   Vacc+=v1.
//         which==2: out=squash(S2).
// ---------------------------------------------------------------------------
__global__ void kv_kernel(int which, float* __restrict__ out) {
    int wid = threadIdx.x >> 5;
    int lane = threadIdx.x & 31;
    int pair = blockIdx.x * (blockDim.x >> 5) + wid;
    if (pair >= B * O) return;
    int idx = pair * VO + lane;

    float s;
    if (which == 0)      s = g_S0[idx] * (1.0f / (float)O);
    else if (which == 1) s = g_S1[idx];
    else                 s = g_S2[idx];

    float sq = s * s;
#pragma unroll
    for (int off = 16; off; off >>= 1)
        sq += __shfl_xor_sync(0xffffffffu, sq, off);

    float scale = (sq / (1.0f + sq)) * rsqrtf(sq + 1e-8f);
    float v = s * scale;

    if (which == 0)      g_Vacc[idx] = v;
    else if (which == 1) g_Vacc[idx] += v;
    else                 out[idx] = v;
}

// ---------------------------------------------------------------------------
extern "C" void kernel_launch(void* const* d_in, const int* in_sizes, int n_in,
                              void* d_out, int out_size) {
    const float* x;
    const float* W;
    if (in_sizes[0] == B * I * VI) {
        x = (const float*)d_in[0];
        W = (const float*)d_in[1];
    } else {
        x = (const float*)d_in[1];
        W = (const float*)d_in[0];
    }
    float* out = (float*)d_out;

    zero_kernel<<<(B * O * VO + 255) / 256, 256>>>();

    // P0: u_hat (fp16) via mma.sync, amortized multi-i CTAs + prefetch
    p0_mma<<<dim3(I / ITER, O / 8), 256>>>(W, x);

    // Iteration 0 (uniform coupling): S0 = sum_i u_hat
    s0_kernel<<<256, 256>>>();
    kv_kernel<<<64, 1024>>>(0, out);   // v0 = squash(S0/64); Vacc = v0

    // Iteration 1: logits = u_hat . v0
    p1_kernel<<<512, 128>>>(1);
    kv_kernel<<<64, 1024>>>(1, out);   // v1 = squash(S1); Vacc = v0 + v1

    // Iteration 2: logits = u_hat . (v0 + v1)
    p1_kernel<<<512, 128>>>(2);
    kv_kernel<<<64, 1024>>>(2, out);   // out = squash(S2)
}